// round 1
// baseline (speedup 1.0000x reference)
#include <cuda_runtime.h>
#include <cstddef>

#define N_TOK 8192
#define DIM   1024

// ---------------- scratch (static device globals; no allocation) ----------------
__device__ float g_q   [(size_t)N_TOK * DIM];   // 32 MB
__device__ float g_k   [(size_t)N_TOK * DIM];   // 32 MB
__device__ float g_gmat[(size_t)N_TOK * DIM];   // 32 MB
__device__ float g_S   [(size_t)N_TOK * N_TOK]; // 256 MB (scores -> probs in place)
__device__ float g_xpart[16 * DIM];
__device__ float g_xbar [DIM];
__device__ float g_muq  [DIM];
__device__ float g_muk  [DIM];
__device__ float g_csg  [DIM];     // column sums of g = N * (xbar @ Wg)
__device__ float g_m    [N_TOK];
__device__ float g_gate [N_TOK];

// ---------------- K0: partial column means of x ----------------
__global__ void colmean_part(const float* __restrict__ x) {
    int col = blockIdx.x * 128 + threadIdx.x;
    int r0  = blockIdx.y * (N_TOK / 16);
    float s = 0.f;
    #pragma unroll 8
    for (int r = r0; r < r0 + N_TOK / 16; r++)
        s += x[(size_t)r * DIM + col];
    g_xpart[blockIdx.y * DIM + col] = s;
}

// ---------------- K1a: finish column mean ----------------
__global__ void colmean_finish() {
    int j = blockIdx.x * 256 + threadIdx.x;
    float s = 0.f;
    #pragma unroll
    for (int p = 0; p < 16; p++) s += g_xpart[p * DIM + j];
    g_xbar[j] = s * (1.0f / (float)N_TOK);
}

// ---------------- K1b: mu_q = xbar@Wq, mu_k = xbar@Wk, csg = N*(xbar@Wg) ----------------
__global__ void mu_kernel(const float* __restrict__ Wq,
                          const float* __restrict__ Wk,
                          const float* __restrict__ Wg) {
    __shared__ float sx[DIM];
    for (int i = threadIdx.x; i < DIM; i += 256) sx[i] = g_xbar[i];
    __syncthreads();
    int j = blockIdx.x * 256 + threadIdx.x;
    const float* W = (blockIdx.y == 0) ? Wq : (blockIdx.y == 1) ? Wk : Wg;
    float acc = 0.f;
    #pragma unroll 8
    for (int d = 0; d < DIM; d++)
        acc = fmaf(sx[d], W[(size_t)d * DIM + j], acc);
    if      (blockIdx.y == 0) g_muq[j] = acc;
    else if (blockIdx.y == 1) g_muk[j] = acc;
    else                      g_csg[j] = acc * (float)N_TOK;
}

// ---------------- K2a: m = x @ Wm_w + b (warp per row) ----------------
__global__ void m_kernel(const float* __restrict__ x,
                         const float* __restrict__ Wm_w,
                         const float* __restrict__ Wm_b) {
    int warp = threadIdx.x >> 5, lane = threadIdx.x & 31;
    int row  = blockIdx.x * 8 + warp;
    const float* xr = x + (size_t)row * DIM;
    float s = 0.f;
    #pragma unroll 8
    for (int t = lane; t < DIM; t += 32) s = fmaf(xr[t], Wm_w[t], s);
    #pragma unroll
    for (int o = 16; o > 0; o >>= 1) s += __shfl_xor_sync(0xffffffffu, s, o);
    if (lane == 0) g_m[row] = s + Wm_b[0];
}

// ---------------- K2b: gate = softmax(m) over tokens (single block) ----------------
__global__ void gate_kernel() {
    __shared__ float red[256];
    int tid = threadIdx.x;
    float mx = -1e30f;
    for (int i = tid; i < N_TOK; i += 256) mx = fmaxf(mx, g_m[i]);
    red[tid] = mx; __syncthreads();
    for (int o = 128; o > 0; o >>= 1) {
        if (tid < o) red[tid] = fmaxf(red[tid], red[tid + o]);
        __syncthreads();
    }
    mx = red[0]; __syncthreads();
    float s = 0.f;
    for (int i = tid; i < N_TOK; i += 256) s += __expf(g_m[i] - mx);
    red[tid] = s; __syncthreads();
    for (int o = 128; o > 0; o >>= 1) {
        if (tid < o) red[tid] += red[tid + o];
        __syncthreads();
    }
    float inv = 1.f / red[0];
    for (int i = tid; i < N_TOK; i += 256)
        g_gate[i] = __expf(g_m[i] - mx) * inv;
}

// ---------------- SGEMM NN: C[M,Nc] = A[M,K] @ B[K,Nc]  (+ epilogues) ----------------
// epilogue: optional subvec (C -= subvec[col]); optional gate/colsum/resid:
//           C += gate[row]*colsum[col] + resid[row,col]
__global__ void __launch_bounds__(256)
sgemm_nn(int M, int Nc, int K,
         const float* __restrict__ A, const float* __restrict__ B,
         float* __restrict__ C,
         const float* __restrict__ subvec,
         const float* __restrict__ gate,
         const float* __restrict__ colsum,
         const float* __restrict__ resid) {
    const int BM = 128, BN = 128, BK = 8, TM = 8, TN = 8;
    __shared__ float As[BK][BM];
    __shared__ float Bs[BK][BN];
    int tid  = threadIdx.x;
    int brow = blockIdx.y, bcol = blockIdx.x;
    const float* Ablk = A + (size_t)brow * BM * K;
    const float* Bblk = B + (size_t)bcol * BN;
    float acc[TM][TN] = {};
    int aRow = tid >> 1;         // 0..127
    int aCol = (tid & 1) * 4;    // 0 or 4
    int bRow = tid >> 5;         // 0..7
    int bCol = (tid & 31) * 4;   // 0..124
    int tr = (tid >> 4) * TM;
    int tc = (tid & 15) * TN;
    for (int k0 = 0; k0 < K; k0 += BK) {
        float4 av = *reinterpret_cast<const float4*>(Ablk + (size_t)aRow * K + k0 + aCol);
        As[aCol + 0][aRow] = av.x; As[aCol + 1][aRow] = av.y;
        As[aCol + 2][aRow] = av.z; As[aCol + 3][aRow] = av.w;
        float4 bv = *reinterpret_cast<const float4*>(Bblk + (size_t)(k0 + bRow) * Nc + bCol);
        *reinterpret_cast<float4*>(&Bs[bRow][bCol]) = bv;
        __syncthreads();
        #pragma unroll
        for (int k = 0; k < BK; k++) {
            float4 a0 = *reinterpret_cast<const float4*>(&As[k][tr]);
            float4 a1 = *reinterpret_cast<const float4*>(&As[k][tr + 4]);
            float4 b0 = *reinterpret_cast<const float4*>(&Bs[k][tc]);
            float4 b1 = *reinterpret_cast<const float4*>(&Bs[k][tc + 4]);
            float ra[TM] = {a0.x, a0.y, a0.z, a0.w, a1.x, a1.y, a1.z, a1.w};
            float rb[TN] = {b0.x, b0.y, b0.z, b0.w, b1.x, b1.y, b1.z, b1.w};
            #pragma unroll
            for (int i = 0; i < TM; i++)
                #pragma unroll
                for (int j = 0; j < TN; j++)
                    acc[i][j] = fmaf(ra[i], rb[j], acc[i][j]);
        }
        __syncthreads();
    }
    #pragma unroll
    for (int i = 0; i < TM; i++) {
        int row = brow * BM + tr + i;
        float gv = gate ? gate[row] : 0.f;
        #pragma unroll
        for (int j = 0; j < TN; j += 4) {
            int col = bcol * BN + tc + j;
            float4 v = make_float4(acc[i][j], acc[i][j + 1], acc[i][j + 2], acc[i][j + 3]);
            if (subvec) {
                v.x -= subvec[col];     v.y -= subvec[col + 1];
                v.z -= subvec[col + 2]; v.w -= subvec[col + 3];
            }
            if (gate) {
                v.x = fmaf(gv, colsum[col],     v.x);
                v.y = fmaf(gv, colsum[col + 1], v.y);
                v.z = fmaf(gv, colsum[col + 2], v.z);
                v.w = fmaf(gv, colsum[col + 3], v.w);
                float4 r = *reinterpret_cast<const float4*>(resid + (size_t)row * Nc + col);
                v.x += r.x; v.y += r.y; v.z += r.z; v.w += r.w;
            }
            *reinterpret_cast<float4*>(C + (size_t)row * Nc + col) = v;
        }
    }
}

// ---------------- SGEMM NT: C[M,Nn] = scale * A[M,K] @ B[Nn,K]^T ----------------
__global__ void __launch_bounds__(256)
sgemm_nt(int M, int Nn, int K,
         const float* __restrict__ A, const float* __restrict__ B,
         float* __restrict__ C, const float* __restrict__ cptr) {
    const int BM = 128, BN = 128, BK = 8, TM = 8, TN = 8;
    __shared__ float As[BK][BM];
    __shared__ float Bs[BK][BN];
    int tid  = threadIdx.x;
    int brow = blockIdx.y, bcol = blockIdx.x;
    const float scale = *cptr;
    const float* Ablk = A + (size_t)brow * BM * K;
    const float* Bblk = B + (size_t)bcol * BN * K;
    float acc[TM][TN] = {};
    int aRow = tid >> 1;
    int aCol = (tid & 1) * 4;
    int tr = (tid >> 4) * TM;
    int tc = (tid & 15) * TN;
    for (int k0 = 0; k0 < K; k0 += BK) {
        float4 av = *reinterpret_cast<const float4*>(Ablk + (size_t)aRow * K + k0 + aCol);
        As[aCol + 0][aRow] = av.x; As[aCol + 1][aRow] = av.y;
        As[aCol + 2][aRow] = av.z; As[aCol + 3][aRow] = av.w;
        float4 bv = *reinterpret_cast<const float4*>(Bblk + (size_t)aRow * K + k0 + aCol);
        Bs[aCol + 0][aRow] = bv.x; Bs[aCol + 1][aRow] = bv.y;
        Bs[aCol + 2][aRow] = bv.z; Bs[aCol + 3][aRow] = bv.w;
        __syncthreads();
        #pragma unroll
        for (int k = 0; k < BK; k++) {
            float4 a0 = *reinterpret_cast<const float4*>(&As[k][tr]);
            float4 a1 = *reinterpret_cast<const float4*>(&As[k][tr + 4]);
            float4 b0 = *reinterpret_cast<const float4*>(&Bs[k][tc]);
            float4 b1 = *reinterpret_cast<const float4*>(&Bs[k][tc + 4]);
            float ra[TM] = {a0.x, a0.y, a0.z, a0.w, a1.x, a1.y, a1.z, a1.w};
            float rb[TN] = {b0.x, b0.y, b0.z, b0.w, b1.x, b1.y, b1.z, b1.w};
            #pragma unroll
            for (int i = 0; i < TM; i++)
                #pragma unroll
                for (int j = 0; j < TN; j++)
                    acc[i][j] = fmaf(ra[i], rb[j], acc[i][j]);
        }
        __syncthreads();
    }
    #pragma unroll
    for (int i = 0; i < TM; i++) {
        int row = brow * BM + tr + i;
        #pragma unroll
        for (int j = 0; j < TN; j += 4) {
            int col = bcol * BN + tc + j;
            float4 v = make_float4(acc[i][j] * scale, acc[i][j + 1] * scale,
                                   acc[i][j + 2] * scale, acc[i][j + 3] * scale);
            *reinterpret_cast<float4*>(C + (size_t)row * Nn + col) = v;
        }
    }
}

// ---------------- K5: in-place row softmax over S (row resident in SMEM) ----------------
__global__ void softmax_row(float* __restrict__ S) {
    __shared__ float buf[N_TOK];   // 32 KB
    __shared__ float red[256];
    int row = blockIdx.x, tid = threadIdx.x;
    float* Sr = S + (size_t)row * N_TOK;
    float mx = -1e30f;
    for (int j = tid; j < N_TOK; j += 256) {
        float v = Sr[j]; buf[j] = v; mx = fmaxf(mx, v);
    }
    red[tid] = mx; __syncthreads();
    for (int o = 128; o > 0; o >>= 1) {
        if (tid < o) red[tid] = fmaxf(red[tid], red[tid + o]);
        __syncthreads();
    }
    mx = red[0]; __syncthreads();
    float s = 0.f;
    for (int j = tid; j < N_TOK; j += 256) {
        float e = __expf(buf[j] - mx); buf[j] = e; s += e;
    }
    red[tid] = s; __syncthreads();
    for (int o = 128; o > 0; o >>= 1) {
        if (tid < o) red[tid] += red[tid + o];
        __syncthreads();
    }
    float inv = 1.f / red[0];
    for (int j = tid; j < N_TOK; j += 256) Sr[j] = buf[j] * inv;
}

// ---------------- launch ----------------
extern "C" void kernel_launch(void* const* d_in, const int* in_sizes, int n_in,
                              void* d_out, int out_size) {
    const float* x    = (const float*)d_in[0];
    const float* Wq   = (const float*)d_in[1];
    const float* Wk   = (const float*)d_in[2];
    const float* Wg   = (const float*)d_in[3];
    const float* Wm_w = (const float*)d_in[4];
    const float* Wm_b = (const float*)d_in[5];
    const float* cp   = (const float*)d_in[6];
    float* out = (float*)d_out;

    float *q, *k, *gm, *S, *muq, *muk, *csg, *gate;
    cudaGetSymbolAddress((void**)&q,    g_q);
    cudaGetSymbolAddress((void**)&k,    g_k);
    cudaGetSymbolAddress((void**)&gm,   g_gmat);
    cudaGetSymbolAddress((void**)&S,    g_S);
    cudaGetSymbolAddress((void**)&muq,  g_muq);
    cudaGetSymbolAddress((void**)&muk,  g_muk);
    cudaGetSymbolAddress((void**)&csg,  g_csg);
    cudaGetSymbolAddress((void**)&gate, g_gate);

    // small statistics
    colmean_part<<<dim3(8, 16), 128>>>(x);
    colmean_finish<<<4, 256>>>();
    mu_kernel<<<dim3(4, 3), 256>>>(Wq, Wk, Wg);
    m_kernel<<<1024, 256>>>(x, Wm_w, Wm_b);
    gate_kernel<<<1, 256>>>();

    // projections: q = x@Wq - mu_q, k = x@Wk - mu_k, g = x@Wg
    sgemm_nn<<<dim3(8, 64), 256>>>(N_TOK, DIM, DIM, x, Wq, q,  muq, nullptr, nullptr, nullptr);
    sgemm_nn<<<dim3(8, 64), 256>>>(N_TOK, DIM, DIM, x, Wk, k,  muk, nullptr, nullptr, nullptr);
    sgemm_nn<<<dim3(8, 64), 256>>>(N_TOK, DIM, DIM, x, Wg, gm, nullptr, nullptr, nullptr, nullptr);

    // scores S = c * q @ k^T
    sgemm_nt<<<dim3(64, 64), 256>>>(N_TOK, N_TOK, DIM, q, k, S, cp);

    // row softmax in place (S -> P)
    softmax_row<<<N_TOK, 256>>>(S);

    // out = P @ g + gate[i]*colsum_g[j] + x
    sgemm_nn<<<dim3(8, 64), 256>>>(N_TOK, DIM, N_TOK, S, gm, out, nullptr, gate, csg, x);
}

// round 5
// speedup vs baseline: 2.7003x; 2.7003x over previous
#include <cuda_runtime.h>
#include <cuda_bf16.h>
#include <cstdint>
#include <cstddef>

typedef __nv_bfloat16 bf16;

#define N_TOK 8192
#define DIM   1024

// ===================== scratch (static device globals) =====================
__device__ __align__(256) bf16  g_xhi [(size_t)N_TOK * DIM];
__device__ __align__(256) bf16  g_xlo [(size_t)N_TOK * DIM];
__device__ __align__(256) bf16  g_wqt_hi[DIM * DIM];
__device__ __align__(256) bf16  g_wqt_lo[DIM * DIM];
__device__ __align__(256) bf16  g_wkt_hi[DIM * DIM];
__device__ __align__(256) bf16  g_wkt_lo[DIM * DIM];
__device__ __align__(256) bf16  g_wgt_hi[DIM * DIM];
__device__ __align__(256) bf16  g_wgt_lo[DIM * DIM];
__device__ __align__(256) bf16  g_qhi [(size_t)N_TOK * DIM];
__device__ __align__(256) bf16  g_qlo [(size_t)N_TOK * DIM];
__device__ __align__(256) bf16  g_khi [(size_t)N_TOK * DIM];
__device__ __align__(256) bf16  g_klo [(size_t)N_TOK * DIM];
__device__ __align__(256) bf16  g_gthi[(size_t)DIM * N_TOK];   // g^T [1024, 8192]
__device__ __align__(256) bf16  g_gtlo[(size_t)DIM * N_TOK];
__device__ __align__(256) float g_S   [(size_t)N_TOK * N_TOK]; // 256 MB
__device__ __align__(256) bf16  g_phi [(size_t)N_TOK * N_TOK]; // 128 MB
__device__ __align__(256) bf16  g_plo [(size_t)N_TOK * N_TOK]; // 128 MB
__device__ float g_xpart[16 * DIM];
__device__ float g_xbar [DIM];
__device__ float g_muq  [DIM];
__device__ float g_muk  [DIM];
__device__ float g_csg  [DIM];
__device__ float g_m    [N_TOK];
__device__ float g_gate [N_TOK];

// ===================== small fp32 kernels =====================
__global__ void colmean_part(const float* __restrict__ x) {
    int col = blockIdx.x * 128 + threadIdx.x;
    int r0  = blockIdx.y * (N_TOK / 16);
    float s = 0.f;
    #pragma unroll 8
    for (int r = r0; r < r0 + N_TOK / 16; r++) s += x[(size_t)r * DIM + col];
    g_xpart[blockIdx.y * DIM + col] = s;
}
__global__ void colmean_finish() {
    int j = blockIdx.x * 256 + threadIdx.x;
    float s = 0.f;
    #pragma unroll
    for (int p = 0; p < 16; p++) s += g_xpart[p * DIM + j];
    g_xbar[j] = s * (1.0f / (float)N_TOK);
}
__global__ void mu_kernel(const float* __restrict__ Wq, const float* __restrict__ Wk,
                          const float* __restrict__ Wg) {
    __shared__ float sx[DIM];
    for (int i = threadIdx.x; i < DIM; i += 256) sx[i] = g_xbar[i];
    __syncthreads();
    int j = blockIdx.x * 256 + threadIdx.x;
    const float* W = (blockIdx.y == 0) ? Wq : (blockIdx.y == 1) ? Wk : Wg;
    float acc = 0.f;
    #pragma unroll 8
    for (int d = 0; d < DIM; d++) acc = fmaf(sx[d], W[(size_t)d * DIM + j], acc);
    if      (blockIdx.y == 0) g_muq[j] = acc;
    else if (blockIdx.y == 1) g_muk[j] = acc;
    else                      g_csg[j] = acc * (float)N_TOK;
}
__global__ void m_kernel(const float* __restrict__ x, const float* __restrict__ Wm_w,
                         const float* __restrict__ Wm_b) {
    int warp = threadIdx.x >> 5, lane = threadIdx.x & 31;
    int row  = blockIdx.x * 8 + warp;
    const float* xr = x + (size_t)row * DIM;
    float s = 0.f;
    #pragma unroll 8
    for (int t = lane; t < DIM; t += 32) s = fmaf(xr[t], Wm_w[t], s);
    #pragma unroll
    for (int o = 16; o > 0; o >>= 1) s += __shfl_xor_sync(0xffffffffu, s, o);
    if (lane == 0) g_m[row] = s + Wm_b[0];
}
__global__ void gate_kernel() {
    __shared__ float red[256];
    int tid = threadIdx.x;
    float mx = -1e30f;
    for (int i = tid; i < N_TOK; i += 256) mx = fmaxf(mx, g_m[i]);
    red[tid] = mx; __syncthreads();
    for (int o = 128; o > 0; o >>= 1) { if (tid < o) red[tid] = fmaxf(red[tid], red[tid + o]); __syncthreads(); }
    mx = red[0]; __syncthreads();
    float s = 0.f;
    for (int i = tid; i < N_TOK; i += 256) s += __expf(g_m[i] - mx);
    red[tid] = s; __syncthreads();
    for (int o = 128; o > 0; o >>= 1) { if (tid < o) red[tid] += red[tid + o]; __syncthreads(); }
    float inv = 1.f / red[0];
    for (int i = tid; i < N_TOK; i += 256) g_gate[i] = __expf(g_m[i] - mx) * inv;
}

// ===================== conversion kernels =====================
__global__ void split4_kernel(const float* __restrict__ in, bf16* __restrict__ hi,
                              bf16* __restrict__ lo, int n4) {
    int i = blockIdx.x * 256 + threadIdx.x;
    if (i >= n4) return;
    float4 v = reinterpret_cast<const float4*>(in)[i];
    bf16 h0 = __float2bfloat16(v.x), h1 = __float2bfloat16(v.y);
    bf16 h2 = __float2bfloat16(v.z), h3 = __float2bfloat16(v.w);
    bf16 l0 = __float2bfloat16(v.x - __bfloat162float(h0));
    bf16 l1 = __float2bfloat16(v.y - __bfloat162float(h1));
    bf16 l2 = __float2bfloat16(v.z - __bfloat162float(h2));
    bf16 l3 = __float2bfloat16(v.w - __bfloat162float(h3));
    reinterpret_cast<__nv_bfloat162*>(hi)[i*2+0] = __nv_bfloat162(h0, h1);
    reinterpret_cast<__nv_bfloat162*>(hi)[i*2+1] = __nv_bfloat162(h2, h3);
    reinterpret_cast<__nv_bfloat162*>(lo)[i*2+0] = __nv_bfloat162(l0, l1);
    reinterpret_cast<__nv_bfloat162*>(lo)[i*2+1] = __nv_bfloat162(l2, l3);
}
__global__ void trans_split_kernel(const float* __restrict__ W, bf16* __restrict__ Thi,
                                   bf16* __restrict__ Tlo) {
    __shared__ float t[32][33];
    int bx = blockIdx.x * 32, by = blockIdx.y * 32;
    #pragma unroll
    for (int i = 0; i < 4; i++)
        t[threadIdx.y + 8*i][threadIdx.x] = W[(size_t)(by + threadIdx.y + 8*i) * DIM + bx + threadIdx.x];
    __syncthreads();
    #pragma unroll
    for (int i = 0; i < 4; i++) {
        float v = t[threadIdx.x][threadIdx.y + 8*i];
        bf16 h = __float2bfloat16(v);
        bf16 l = __float2bfloat16(v - __bfloat162float(h));
        size_t o = (size_t)(bx + threadIdx.y + 8*i) * DIM + by + threadIdx.x;
        Thi[o] = h; Tlo[o] = l;
    }
}

// ===================== mma.sync bf16 GEMM with 3-phase split =====================
// C[M,Nc] = sum_k A[m,k]*B[n,k]  (B stored [Nc][K], i.e. "col" operand)
// MODE 0: outHi/outLo bf16 split = acc - subvec[col] (subvec optional)
// MODE 2: outF = acc * (*scaleptr)
// MODE 3: outF = acc + gate[row]*csum[col] + resid[row*DIM+col]
#define BK      32
#define SROWE   40                       // padded row stride (elems) -> 80 bytes
#define STAGE_B (128 * SROWE * 2 * 2)    // A half + B half = 20480 bytes
#define SMEM_GEMM (4 * STAGE_B)          // 81920

__device__ __forceinline__ uint32_t smem_u32(const void* p) {
    uint32_t addr;
    asm("{ .reg .u64 tmp; cvta.to.shared.u64 tmp, %1; cvt.u32.u64 %0, tmp; }"
        : "=r"(addr) : "l"(p));
    return addr;
}
#define CP_ASYNC16(dst_u32, src_ptr) \
    asm volatile("cp.async.cg.shared.global [%0], [%1], 16;" :: "r"(dst_u32), "l"(src_ptr) : "memory")
#define CP_COMMIT() asm volatile("cp.async.commit_group;" ::: "memory")
#define CP_WAIT2()  asm volatile("cp.async.wait_group 2;" ::: "memory")

template<int MODE>
__global__ void __launch_bounds__(128, 2)
gemm3(int K,
      const bf16* __restrict__ Ahi, const bf16* __restrict__ Alo,
      const bf16* __restrict__ Bhi, const bf16* __restrict__ Blo,
      float* __restrict__ outF, bf16* __restrict__ outHi, bf16* __restrict__ outLo,
      const float* __restrict__ subvec, const float* __restrict__ scaleptr,
      const float* __restrict__ gate, const float* __restrict__ csum,
      const float* __restrict__ resid, int ldo)
{
    extern __shared__ char sm[];
    const int tid  = threadIdx.x;
    const int wid  = tid >> 5, lane = tid & 31;
    const int gid  = lane >> 2, tig = lane & 3;
    const int wm   = wid & 1, wn = wid >> 1;       // warp 64x64 tile: 2x2 layout
    const int row0 = blockIdx.y * 128;
    const int col0 = blockIdx.x * 128;

    const int CPP = K / BK;
    const int NCH = 3 * CPP;

    float acc[4][8][4];
    #pragma unroll
    for (int i = 0; i < 4; i++)
        #pragma unroll
        for (int j = 0; j < 8; j++)
            #pragma unroll
            for (int t = 0; t < 4; t++) acc[i][j][t] = 0.f;

    auto loadChunk = [&](int c) {
        int ph = c / CPP, kk = (c % CPP) * BK;
        const bf16* Ap = (ph == 2) ? Alo : Ahi;
        const bf16* Bp = (ph == 1) ? Blo : Bhi;
        uint32_t st = smem_u32(sm) + (c & 3) * STAGE_B;
        #pragma unroll
        for (int it = 0; it < 4; ++it) {
            int idx = it * 128 + tid;
            int r = idx >> 2, ch = idx & 3;
            const bf16* ga = Ap + (size_t)(row0 + r) * K + kk + ch * 8;
            CP_ASYNC16(st + r * 80 + ch * 16, ga);
            const bf16* gb = Bp + (size_t)(col0 + r) * K + kk + ch * 8;
            CP_ASYNC16(st + 10240 + r * 80 + ch * 16, gb);
        }
    };

    loadChunk(0); CP_COMMIT();
    loadChunk(1); CP_COMMIT();
    loadChunk(2); CP_COMMIT();

    for (int c = 0; c < NCH; ++c) {
        CP_WAIT2();
        __syncthreads();
        // compute slab c
        {
            const char* sA = sm + (c & 3) * STAGE_B + (size_t)(wm * 64) * 80;
            const char* sB = sm + (c & 3) * STAGE_B + 10240 + (size_t)(wn * 64) * 80;
            #pragma unroll
            for (int k2 = 0; k2 < BK; k2 += 16) {
                uint32_t a[4][4], b[8][2];
                int co = (k2 + tig * 2) * 2;           // byte offset of k within row
                #pragma unroll
                for (int mt = 0; mt < 4; ++mt) {
                    const char* p = sA + (mt * 16 + gid) * 80 + co;
                    a[mt][0] = *(const uint32_t*)(p);
                    a[mt][1] = *(const uint32_t*)(p + 8 * 80);
                    a[mt][2] = *(const uint32_t*)(p + 16);
                    a[mt][3] = *(const uint32_t*)(p + 8 * 80 + 16);
                }
                #pragma unroll
                for (int nt = 0; nt < 8; ++nt) {
                    const char* p = sB + (nt * 8 + gid) * 80 + co;
                    b[nt][0] = *(const uint32_t*)(p);
                    b[nt][1] = *(const uint32_t*)(p + 16);
                }
                #pragma unroll
                for (int mt = 0; mt < 4; ++mt)
                    #pragma unroll
                    for (int nt = 0; nt < 8; ++nt)
                        asm volatile(
                            "mma.sync.aligned.m16n8k16.row.col.f32.bf16.bf16.f32 "
                            "{%0,%1,%2,%3}, {%4,%5,%6,%7}, {%8,%9}, {%0,%1,%2,%3};"
                            : "+f"(acc[mt][nt][0]), "+f"(acc[mt][nt][1]),
                              "+f"(acc[mt][nt][2]), "+f"(acc[mt][nt][3])
                            : "r"(a[mt][0]), "r"(a[mt][1]), "r"(a[mt][2]), "r"(a[mt][3]),
                              "r"(b[nt][0]), "r"(b[nt][1]));
            }
        }
        if (c + 3 < NCH) loadChunk(c + 3);
        CP_COMMIT();
    }

    // ---------------- epilogue ----------------
    float scale = (MODE == 2) ? *scaleptr : 1.0f;
    #pragma unroll
    for (int mt = 0; mt < 4; ++mt) {
        int r1 = row0 + wm * 64 + mt * 16 + gid;
        int r2 = r1 + 8;
        float gv1 = 0.f, gv2 = 0.f;
        if (MODE == 3) { gv1 = gate[r1]; gv2 = gate[r2]; }
        #pragma unroll
        for (int nt = 0; nt < 8; ++nt) {
            int col = col0 + wn * 64 + nt * 8 + tig * 2;
            float c0 = acc[mt][nt][0], c1 = acc[mt][nt][1];
            float c2 = acc[mt][nt][2], c3 = acc[mt][nt][3];
            if (MODE == 0) {
                if (subvec) {
                    float s0 = subvec[col], s1 = subvec[col + 1];
                    c0 -= s0; c1 -= s1; c2 -= s0; c3 -= s1;
                }
                bf16 h0 = __float2bfloat16(c0), h1 = __float2bfloat16(c1);
                bf16 h2 = __float2bfloat16(c2), h3 = __float2bfloat16(c3);
                bf16 l0 = __float2bfloat16(c0 - __bfloat162float(h0));
                bf16 l1 = __float2bfloat16(c1 - __bfloat162float(h1));
                bf16 l2 = __float2bfloat16(c2 - __bfloat162float(h2));
                bf16 l3 = __float2bfloat16(c3 - __bfloat162float(h3));
                *reinterpret_cast<__nv_bfloat162*>(outHi + (size_t)r1 * ldo + col) = __nv_bfloat162(h0, h1);
                *reinterpret_cast<__nv_bfloat162*>(outHi + (size_t)r2 * ldo + col) = __nv_bfloat162(h2, h3);
                *reinterpret_cast<__nv_bfloat162*>(outLo + (size_t)r1 * ldo + col) = __nv_bfloat162(l0, l1);
                *reinterpret_cast<__nv_bfloat162*>(outLo + (size_t)r2 * ldo + col) = __nv_bfloat162(l2, l3);
            } else if (MODE == 2) {
                *reinterpret_cast<float2*>(outF + (size_t)r1 * ldo + col) = make_float2(c0 * scale, c1 * scale);
                *reinterpret_cast<float2*>(outF + (size_t)r2 * ldo + col) = make_float2(c2 * scale, c3 * scale);
            } else {
                float cs0 = csum[col], cs1 = csum[col + 1];
                float2 x1 = *reinterpret_cast<const float2*>(resid + (size_t)r1 * DIM + col);
                float2 x2 = *reinterpret_cast<const float2*>(resid + (size_t)r2 * DIM + col);
                *reinterpret_cast<float2*>(outF + (size_t)r1 * ldo + col) =
                    make_float2(c0 + gv1 * cs0 + x1.x, c1 + gv1 * cs1 + x1.y);
                *reinterpret_cast<float2*>(outF + (size_t)r2 * ldo + col) =
                    make_float2(c2 + gv2 * cs0 + x2.x, c3 + gv2 * cs1 + x2.y);
            }
        }
    }
}

// ===================== fused row softmax + bf16 split =====================
__global__ void softmax_split(const float* __restrict__ S, bf16* __restrict__ Phi,
                              bf16* __restrict__ Plo) {
    __shared__ float buf[N_TOK];
    __shared__ float red[256];
    int row = blockIdx.x, tid = threadIdx.x;
    const float* Sr = S + (size_t)row * N_TOK;
    float mx = -1e30f;
    for (int j = tid; j < N_TOK; j += 256) { float v = Sr[j]; buf[j] = v; mx = fmaxf(mx, v); }
    red[tid] = mx; __syncthreads();
    for (int o = 128; o > 0; o >>= 1) { if (tid < o) red[tid] = fmaxf(red[tid], red[tid + o]); __syncthreads(); }
    mx = red[0]; __syncthreads();
    float s = 0.f;
    for (int j = tid; j < N_TOK; j += 256) { float e = __expf(buf[j] - mx); buf[j] = e; s += e; }
    red[tid] = s; __syncthreads();
    for (int o = 128; o > 0; o >>= 1) { if (tid < o) red[tid] += red[tid + o]; __syncthreads(); }
    float inv = 1.f / red[0];
    for (int j = tid; j < N_TOK; j += 256) {
        float p = buf[j] * inv;
        bf16 h = __float2bfloat16(p);
        bf16 l = __float2bfloat16(p - __bfloat162float(h));
        size_t o = (size_t)row * N_TOK + j;
        Phi[o] = h; Plo[o] = l;
    }
}

// ===================== launch =====================
extern "C" void kernel_launch(void* const* d_in, const int* in_sizes, int n_in,
                              void* d_out, int out_size) {
    const float* x    = (const float*)d_in[0];
    const float* Wq   = (const float*)d_in[1];
    const float* Wk   = (const float*)d_in[2];
    const float* Wg   = (const float*)d_in[3];
    const float* Wm_w = (const float*)d_in[4];
    const float* Wm_b = (const float*)d_in[5];
    const float* cp   = (const float*)d_in[6];
    float* out = (float*)d_out;

    bf16 *xhi,*xlo,*wqh,*wql,*wkh,*wkl,*wgh,*wgl,*qhi,*qlo,*khi,*klo,*gth,*gtl,*phi,*plo;
    float *S,*muq,*muk,*csg,*gate;
    cudaGetSymbolAddress((void**)&xhi, g_xhi);   cudaGetSymbolAddress((void**)&xlo, g_xlo);
    cudaGetSymbolAddress((void**)&wqh, g_wqt_hi);cudaGetSymbolAddress((void**)&wql, g_wqt_lo);
    cudaGetSymbolAddress((void**)&wkh, g_wkt_hi);cudaGetSymbolAddress((void**)&wkl, g_wkt_lo);
    cudaGetSymbolAddress((void**)&wgh, g_wgt_hi);cudaGetSymbolAddress((void**)&wgl, g_wgt_lo);
    cudaGetSymbolAddress((void**)&qhi, g_qhi);   cudaGetSymbolAddress((void**)&qlo, g_qlo);
    cudaGetSymbolAddress((void**)&khi, g_khi);   cudaGetSymbolAddress((void**)&klo, g_klo);
    cudaGetSymbolAddress((void**)&gth, g_gthi);  cudaGetSymbolAddress((void**)&gtl, g_gtlo);
    cudaGetSymbolAddress((void**)&phi, g_phi);   cudaGetSymbolAddress((void**)&plo, g_plo);
    cudaGetSymbolAddress((void**)&S,   g_S);
    cudaGetSymbolAddress((void**)&muq, g_muq);   cudaGetSymbolAddress((void**)&muk, g_muk);
    cudaGetSymbolAddress((void**)&csg, g_csg);   cudaGetSymbolAddress((void**)&gate, g_gate);

    cudaFuncSetAttribute(gemm3<0>, cudaFuncAttributeMaxDynamicSharedMemorySize, SMEM_GEMM);
    cudaFuncSetAttribute(gemm3<2>, cudaFuncAttributeMaxDynamicSharedMemorySize, SMEM_GEMM);
    cudaFuncSetAttribute(gemm3<3>, cudaFuncAttributeMaxDynamicSharedMemorySize, SMEM_GEMM);

    // stats + conversions
    colmean_part<<<dim3(8, 16), 128>>>(x);
    colmean_finish<<<4, 256>>>();
    mu_kernel<<<dim3(4, 3), 256>>>(Wq, Wk, Wg);
    m_kernel<<<1024, 256>>>(x, Wm_w, Wm_b);
    gate_kernel<<<1, 256>>>();
    split4_kernel<<<(N_TOK * DIM / 4 + 255) / 256, 256>>>(x, xhi, xlo, N_TOK * DIM / 4);
    trans_split_kernel<<<dim3(32, 32), dim3(32, 8)>>>(Wq, wqh, wql);
    trans_split_kernel<<<dim3(32, 32), dim3(32, 8)>>>(Wk, wkh, wkl);
    trans_split_kernel<<<dim3(32, 32), dim3(32, 8)>>>(Wg, wgh, wgl);

    // q = x@Wq - muq ; k = x@Wk - muk   (A = x [8192,1024], B = W^T [1024,1024])
    gemm3<0><<<dim3(DIM / 128, N_TOK / 128), 128, SMEM_GEMM>>>(
        DIM, xhi, xlo, wqh, wql, nullptr, qhi, qlo, muq, nullptr, nullptr, nullptr, nullptr, DIM);
    gemm3<0><<<dim3(DIM / 128, N_TOK / 128), 128, SMEM_GEMM>>>(
        DIM, xhi, xlo, wkh, wkl, nullptr, khi, klo, muk, nullptr, nullptr, nullptr, nullptr, DIM);
    // gT = Wg^T @ x^T : A = Wg^T [1024,1024], B = x [8192,1024] -> out [1024, 8192]
    gemm3<0><<<dim3(N_TOK / 128, DIM / 128), 128, SMEM_GEMM>>>(
        DIM, wgh, wgl, xhi, xlo, nullptr, gth, gtl, nullptr, nullptr, nullptr, nullptr, nullptr, N_TOK);

    // S = c * q @ k^T   (A = q [8192,1024], B = k [8192,1024])
    gemm3<2><<<dim3(N_TOK / 128, N_TOK / 128), 128, SMEM_GEMM>>>(
        DIM, qhi, qlo, khi, klo, S, nullptr, nullptr, nullptr, cp, nullptr, nullptr, nullptr, N_TOK);

    // row softmax + split to bf16
    softmax_split<<<N_TOK, 256>>>(S, phi, plo);

    // out = P @ g + gate[row]*csg[col] + x   (A = P [8192,8192], B = gT [1024,8192])
    gemm3<3><<<dim3(DIM / 128, N_TOK / 128), 128, SMEM_GEMM>>>(
        N_TOK, phi, plo, gth, gtl, out, nullptr, nullptr, nullptr, nullptr, gate, csg, x, DIM);
}

// round 6
// speedup vs baseline: 6.6025x; 2.4451x over previous
#include <cuda_runtime.h>
#include <cuda_bf16.h>
#include <cstdint>
#include <cstddef>

typedef __nv_bfloat16 bf16;

#define N_TOK 8192
#define DIM   1024

// ===================== scratch (static device globals) =====================
__device__ __align__(256) bf16  g_xb  [(size_t)N_TOK * DIM];
__device__ __align__(256) bf16  g_wqt [DIM * DIM];
__device__ __align__(256) bf16  g_wkt [DIM * DIM];
__device__ __align__(256) bf16  g_wgt [DIM * DIM];
__device__ __align__(256) bf16  g_qb  [(size_t)N_TOK * DIM];
__device__ __align__(256) bf16  g_kb  [(size_t)N_TOK * DIM];
__device__ __align__(256) bf16  g_gt  [(size_t)DIM * N_TOK];   // g^T [1024, 8192]
__device__ __align__(256) bf16  g_P   [(size_t)N_TOK * N_TOK]; // scores -> probs, bf16, 128 MB
__device__ float g_xpart[16 * DIM];
__device__ float g_xbar [DIM];
__device__ float g_muq  [DIM];
__device__ float g_muk  [DIM];
__device__ float g_csg  [DIM];
__device__ float g_m    [N_TOK];
__device__ float g_gate [N_TOK];

// ===================== small fp32 kernels =====================
__global__ void colmean_part(const float* __restrict__ x) {
    int col = blockIdx.x * 128 + threadIdx.x;
    int r0  = blockIdx.y * (N_TOK / 16);
    float s = 0.f;
    #pragma unroll 8
    for (int r = r0; r < r0 + N_TOK / 16; r++) s += x[(size_t)r * DIM + col];
    g_xpart[blockIdx.y * DIM + col] = s;
}
__global__ void colmean_finish() {
    int j = blockIdx.x * 256 + threadIdx.x;
    float s = 0.f;
    #pragma unroll
    for (int p = 0; p < 16; p++) s += g_xpart[p * DIM + j];
    g_xbar[j] = s * (1.0f / (float)N_TOK);
}
__global__ void mu_kernel(const float* __restrict__ Wq, const float* __restrict__ Wk,
                          const float* __restrict__ Wg) {
    __shared__ float sx[DIM];
    for (int i = threadIdx.x; i < DIM; i += 256) sx[i] = g_xbar[i];
    __syncthreads();
    int j = blockIdx.x * 256 + threadIdx.x;
    const float* W = (blockIdx.y == 0) ? Wq : (blockIdx.y == 1) ? Wk : Wg;
    float acc = 0.f;
    #pragma unroll 8
    for (int d = 0; d < DIM; d++) acc = fmaf(sx[d], W[(size_t)d * DIM + j], acc);
    if      (blockIdx.y == 0) g_muq[j] = acc;
    else if (blockIdx.y == 1) g_muk[j] = acc;
    else                      g_csg[j] = acc * (float)N_TOK;
}
__global__ void m_kernel(const float* __restrict__ x, const float* __restrict__ Wm_w,
                         const float* __restrict__ Wm_b) {
    int warp = threadIdx.x >> 5, lane = threadIdx.x & 31;
    int row  = blockIdx.x * 8 + warp;
    const float* xr = x + (size_t)row * DIM;
    float s = 0.f;
    #pragma unroll 8
    for (int t = lane; t < DIM; t += 32) s = fmaf(xr[t], Wm_w[t], s);
    #pragma unroll
    for (int o = 16; o > 0; o >>= 1) s += __shfl_xor_sync(0xffffffffu, s, o);
    if (lane == 0) g_m[row] = s + Wm_b[0];
}
__global__ void gate_kernel() {
    __shared__ float red[256];
    int tid = threadIdx.x;
    float mx = -1e30f;
    for (int i = tid; i < N_TOK; i += 256) mx = fmaxf(mx, g_m[i]);
    red[tid] = mx; __syncthreads();
    for (int o = 128; o > 0; o >>= 1) { if (tid < o) red[tid] = fmaxf(red[tid], red[tid + o]); __syncthreads(); }
    mx = red[0]; __syncthreads();
    float s = 0.f;
    for (int i = tid; i < N_TOK; i += 256) s += __expf(g_m[i] - mx);
    red[tid] = s; __syncthreads();
    for (int o = 128; o > 0; o >>= 1) { if (tid < o) red[tid] += red[tid + o]; __syncthreads(); }
    float inv = 1.f / red[0];
    for (int i = tid; i < N_TOK; i += 256) g_gate[i] = __expf(g_m[i] - mx) * inv;
}

// ===================== conversion kernels =====================
__global__ void tobf16_kernel(const float* __restrict__ in, bf16* __restrict__ outb, int n4) {
    int i = blockIdx.x * 256 + threadIdx.x;
    if (i >= n4) return;
    float4 v = reinterpret_cast<const float4*>(in)[i];
    reinterpret_cast<__nv_bfloat162*>(outb)[i*2+0] =
        __nv_bfloat162(__float2bfloat16(v.x), __float2bfloat16(v.y));
    reinterpret_cast<__nv_bfloat162*>(outb)[i*2+1] =
        __nv_bfloat162(__float2bfloat16(v.z), __float2bfloat16(v.w));
}
__global__ void trans_bf16_kernel(const float* __restrict__ W, bf16* __restrict__ T) {
    __shared__ float t[32][33];
    int bx = blockIdx.x * 32, by = blockIdx.y * 32;
    #pragma unroll
    for (int i = 0; i < 4; i++)
        t[threadIdx.y + 8*i][threadIdx.x] = W[(size_t)(by + threadIdx.y + 8*i) * DIM + bx + threadIdx.x];
    __syncthreads();
    #pragma unroll
    for (int i = 0; i < 4; i++)
        T[(size_t)(bx + threadIdx.y + 8*i) * DIM + by + threadIdx.x] =
            __float2bfloat16(t[threadIdx.x][threadIdx.y + 8*i]);
}

// ===================== mma.sync bf16 GEMM (single phase) =====================
// C[M,Nc] = sum_k A[m,k]*B[n,k]  (B stored [Nc][K])
// MODE 0: outB = bf16(acc - subvec[col])  (subvec optional)
// MODE 2: outB = bf16(acc * (*scaleptr))
// MODE 3: outF = acc + gate[row]*csum[col] + resid[row*DIM+col]
#define BK      32
#define STAGE_B (128 * 40 * 2 * 2)       // A half + B half = 20480 bytes
#define SMEM_GEMM (4 * STAGE_B)          // 81920

__device__ __forceinline__ uint32_t smem_u32(const void* p) {
    uint32_t addr;
    asm("{ .reg .u64 tmp; cvta.to.shared.u64 tmp, %1; cvt.u32.u64 %0, tmp; }"
        : "=r"(addr) : "l"(p));
    return addr;
}
#define CP_ASYNC16(dst_u32, src_ptr) \
    asm volatile("cp.async.cg.shared.global [%0], [%1], 16;" :: "r"(dst_u32), "l"(src_ptr) : "memory")
#define CP_COMMIT() asm volatile("cp.async.commit_group;" ::: "memory")
#define CP_WAIT2()  asm volatile("cp.async.wait_group 2;" ::: "memory")

template<int MODE>
__global__ void __launch_bounds__(128, 2)
gemm1(int K,
      const bf16* __restrict__ A, const bf16* __restrict__ B,
      float* __restrict__ outF, bf16* __restrict__ outB,
      const float* __restrict__ subvec, const float* __restrict__ scaleptr,
      const float* __restrict__ gate, const float* __restrict__ csum,
      const float* __restrict__ resid, int ldo)
{
    extern __shared__ char sm[];
    const int tid  = threadIdx.x;
    const int wid  = tid >> 5, lane = tid & 31;
    const int gid  = lane >> 2, tig = lane & 3;
    const int wm   = wid & 1, wn = wid >> 1;       // warp 64x64 tile: 2x2 layout
    const int row0 = blockIdx.y * 128;
    const int col0 = blockIdx.x * 128;
    const int NCH  = K / BK;

    float acc[4][8][4];
    #pragma unroll
    for (int i = 0; i < 4; i++)
        #pragma unroll
        for (int j = 0; j < 8; j++)
            #pragma unroll
            for (int t = 0; t < 4; t++) acc[i][j][t] = 0.f;

    auto loadChunk = [&](int c) {
        int kk = c * BK;
        uint32_t st = smem_u32(sm) + (c & 3) * STAGE_B;
        #pragma unroll
        for (int it = 0; it < 4; ++it) {
            int idx = it * 128 + tid;
            int r = idx >> 2, ch = idx & 3;
            const bf16* ga = A + (size_t)(row0 + r) * K + kk + ch * 8;
            CP_ASYNC16(st + r * 80 + ch * 16, ga);
            const bf16* gb = B + (size_t)(col0 + r) * K + kk + ch * 8;
            CP_ASYNC16(st + 10240 + r * 80 + ch * 16, gb);
        }
    };

    loadChunk(0); CP_COMMIT();
    loadChunk(1); CP_COMMIT();
    loadChunk(2); CP_COMMIT();

    for (int c = 0; c < NCH; ++c) {
        CP_WAIT2();
        __syncthreads();
        {
            const char* sA = sm + (c & 3) * STAGE_B + (size_t)(wm * 64) * 80;
            const char* sB = sm + (c & 3) * STAGE_B + 10240 + (size_t)(wn * 64) * 80;
            #pragma unroll
            for (int k2 = 0; k2 < BK; k2 += 16) {
                uint32_t a[4][4], b[8][2];
                int co = (k2 + tig * 2) * 2;
                #pragma unroll
                for (int mt = 0; mt < 4; ++mt) {
                    const char* p = sA + (mt * 16 + gid) * 80 + co;
                    a[mt][0] = *(const uint32_t*)(p);
                    a[mt][1] = *(const uint32_t*)(p + 8 * 80);
                    a[mt][2] = *(const uint32_t*)(p + 16);
                    a[mt][3] = *(const uint32_t*)(p + 8 * 80 + 16);
                }
                #pragma unroll
                for (int nt = 0; nt < 8; ++nt) {
                    const char* p = sB + (nt * 8 + gid) * 80 + co;
                    b[nt][0] = *(const uint32_t*)(p);
                    b[nt][1] = *(const uint32_t*)(p + 16);
                }
                #pragma unroll
                for (int mt = 0; mt < 4; ++mt)
                    #pragma unroll
                    for (int nt = 0; nt < 8; ++nt)
                        asm volatile(
                            "mma.sync.aligned.m16n8k16.row.col.f32.bf16.bf16.f32 "
                            "{%0,%1,%2,%3}, {%4,%5,%6,%7}, {%8,%9}, {%0,%1,%2,%3};"
                            : "+f"(acc[mt][nt][0]), "+f"(acc[mt][nt][1]),
                              "+f"(acc[mt][nt][2]), "+f"(acc[mt][nt][3])
                            : "r"(a[mt][0]), "r"(a[mt][1]), "r"(a[mt][2]), "r"(a[mt][3]),
                              "r"(b[nt][0]), "r"(b[nt][1]));
            }
        }
        if (c + 3 < NCH) loadChunk(c + 3);
        CP_COMMIT();
    }

    // ---------------- epilogue ----------------
    float scale = (MODE == 2) ? *scaleptr : 1.0f;
    #pragma unroll
    for (int mt = 0; mt < 4; ++mt) {
        int r1 = row0 + wm * 64 + mt * 16 + gid;
        int r2 = r1 + 8;
        float gv1 = 0.f, gv2 = 0.f;
        if (MODE == 3) { gv1 = gate[r1]; gv2 = gate[r2]; }
        #pragma unroll
        for (int nt = 0; nt < 8; ++nt) {
            int col = col0 + wn * 64 + nt * 8 + tig * 2;
            float c0 = acc[mt][nt][0], c1 = acc[mt][nt][1];
            float c2 = acc[mt][nt][2], c3 = acc[mt][nt][3];
            if (MODE == 0) {
                if (subvec) {
                    float s0 = subvec[col], s1 = subvec[col + 1];
                    c0 -= s0; c1 -= s1; c2 -= s0; c3 -= s1;
                }
                *reinterpret_cast<__nv_bfloat162*>(outB + (size_t)r1 * ldo + col) =
                    __nv_bfloat162(__float2bfloat16(c0), __float2bfloat16(c1));
                *reinterpret_cast<__nv_bfloat162*>(outB + (size_t)r2 * ldo + col) =
                    __nv_bfloat162(__float2bfloat16(c2), __float2bfloat16(c3));
            } else if (MODE == 2) {
                *reinterpret_cast<__nv_bfloat162*>(outB + (size_t)r1 * ldo + col) =
                    __nv_bfloat162(__float2bfloat16(c0 * scale), __float2bfloat16(c1 * scale));
                *reinterpret_cast<__nv_bfloat162*>(outB + (size_t)r2 * ldo + col) =
                    __nv_bfloat162(__float2bfloat16(c2 * scale), __float2bfloat16(c3 * scale));
            } else {
                float cs0 = csum[col], cs1 = csum[col + 1];
                float2 x1 = *reinterpret_cast<const float2*>(resid + (size_t)r1 * DIM + col);
                float2 x2 = *reinterpret_cast<const float2*>(resid + (size_t)r2 * DIM + col);
                *reinterpret_cast<float2*>(outF + (size_t)r1 * ldo + col) =
                    make_float2(c0 + gv1 * cs0 + x1.x, c1 + gv1 * cs1 + x1.y);
                *reinterpret_cast<float2*>(outF + (size_t)r2 * ldo + col) =
                    make_float2(c2 + gv2 * cs0 + x2.x, c3 + gv2 * cs1 + x2.y);
            }
        }
    }
}

// ===================== in-place row softmax on bf16 scores =====================
__global__ void softmax_bf16(bf16* __restrict__ P) {
    __shared__ float buf[N_TOK];   // 32 KB
    __shared__ float red[256];
    int row = blockIdx.x, tid = threadIdx.x;
    bf16* Pr = P + (size_t)row * N_TOK;
    float mx = -1e30f;
    for (int j = tid; j < N_TOK; j += 256) {
        float v = __bfloat162float(Pr[j]); buf[j] = v; mx = fmaxf(mx, v);
    }
    red[tid] = mx; __syncthreads();
    for (int o = 128; o > 0; o >>= 1) { if (tid < o) red[tid] = fmaxf(red[tid], red[tid + o]); __syncthreads(); }
    mx = red[0]; __syncthreads();
    float s = 0.f;
    for (int j = tid; j < N_TOK; j += 256) { float e = __expf(buf[j] - mx); buf[j] = e; s += e; }
    red[tid] = s; __syncthreads();
    for (int o = 128; o > 0; o >>= 1) { if (tid < o) red[tid] += red[tid + o]; __syncthreads(); }
    float inv = 1.f / red[0];
    for (int j = tid; j < N_TOK; j += 256) Pr[j] = __float2bfloat16(buf[j] * inv);
}

// ===================== launch =====================
extern "C" void kernel_launch(void* const* d_in, const int* in_sizes, int n_in,
                              void* d_out, int out_size) {
    const float* x    = (const float*)d_in[0];
    const float* Wq   = (const float*)d_in[1];
    const float* Wk   = (const float*)d_in[2];
    const float* Wg   = (const float*)d_in[3];
    const float* Wm_w = (const float*)d_in[4];
    const float* Wm_b = (const float*)d_in[5];
    const float* cp   = (const float*)d_in[6];
    float* out = (float*)d_out;

    bf16 *xb,*wqt,*wkt,*wgt,*qb,*kb,*gt,*P;
    float *muq,*muk,*csg,*gate;
    cudaGetSymbolAddress((void**)&xb,  g_xb);
    cudaGetSymbolAddress((void**)&wqt, g_wqt);
    cudaGetSymbolAddress((void**)&wkt, g_wkt);
    cudaGetSymbolAddress((void**)&wgt, g_wgt);
    cudaGetSymbolAddress((void**)&qb,  g_qb);
    cudaGetSymbolAddress((void**)&kb,  g_kb);
    cudaGetSymbolAddress((void**)&gt,  g_gt);
    cudaGetSymbolAddress((void**)&P,   g_P);
    cudaGetSymbolAddress((void**)&muq, g_muq);
    cudaGetSymbolAddress((void**)&muk, g_muk);
    cudaGetSymbolAddress((void**)&csg, g_csg);
    cudaGetSymbolAddress((void**)&gate, g_gate);

    cudaFuncSetAttribute(gemm1<0>, cudaFuncAttributeMaxDynamicSharedMemorySize, SMEM_GEMM);
    cudaFuncSetAttribute(gemm1<2>, cudaFuncAttributeMaxDynamicSharedMemorySize, SMEM_GEMM);
    cudaFuncSetAttribute(gemm1<3>, cudaFuncAttributeMaxDynamicSharedMemorySize, SMEM_GEMM);

    // stats + conversions
    colmean_part<<<dim3(8, 16), 128>>>(x);
    colmean_finish<<<4, 256>>>();
    mu_kernel<<<dim3(4, 3), 256>>>(Wq, Wk, Wg);
    m_kernel<<<1024, 256>>>(x, Wm_w, Wm_b);
    gate_kernel<<<1, 256>>>();
    tobf16_kernel<<<(N_TOK * DIM / 4 + 255) / 256, 256>>>(x, xb, N_TOK * DIM / 4);
    trans_bf16_kernel<<<dim3(32, 32), dim3(32, 8)>>>(Wq, wqt);
    trans_bf16_kernel<<<dim3(32, 32), dim3(32, 8)>>>(Wk, wkt);
    trans_bf16_kernel<<<dim3(32, 32), dim3(32, 8)>>>(Wg, wgt);

    // q = x@Wq - muq ; k = x@Wk - muk
    gemm1<0><<<dim3(DIM / 128, N_TOK / 128), 128, SMEM_GEMM>>>(
        DIM, xb, wqt, nullptr, qb, muq, nullptr, nullptr, nullptr, nullptr, DIM);
    gemm1<0><<<dim3(DIM / 128, N_TOK / 128), 128, SMEM_GEMM>>>(
        DIM, xb, wkt, nullptr, kb, muk, nullptr, nullptr, nullptr, nullptr, DIM);
    // gT = Wg^T @ x^T : out [1024, 8192]
    gemm1<0><<<dim3(N_TOK / 128, DIM / 128), 128, SMEM_GEMM>>>(
        DIM, wgt, xb, nullptr, gt, nullptr, nullptr, nullptr, nullptr, nullptr, N_TOK);

    // P = bf16(c * q @ k^T)
    gemm1<2><<<dim3(N_TOK / 128, N_TOK / 128), 128, SMEM_GEMM>>>(
        DIM, qb, kb, nullptr, P, nullptr, cp, nullptr, nullptr, nullptr, N_TOK);

    // row softmax in place
    softmax_bf16<<<N_TOK, 256>>>(P);

    // out = P @ g + gate[row]*csg[col] + x
    gemm1<3><<<dim3(DIM / 128, N_TOK / 128), 128, SMEM_GEMM>>>(
        N_TOK, P, gt, out, nullptr, nullptr, nullptr, gate, csg, x, DIM);
}

// round 7
// speedup vs baseline: 7.8336x; 1.1865x over previous
#include <cuda_runtime.h>
#include <cuda_bf16.h>
#include <cstdint>
#include <cstddef>

typedef __nv_bfloat16 bf16;

#define N_TOK 8192
#define DIM   1024

// ===================== scratch (static device globals) =====================
__device__ __align__(256) bf16  g_xb  [(size_t)N_TOK * DIM];
__device__ __align__(256) bf16  g_wqt [DIM * DIM];
__device__ __align__(256) bf16  g_wkt [DIM * DIM];
__device__ __align__(256) bf16  g_wgt [DIM * DIM];
__device__ __align__(256) bf16  g_qb  [(size_t)N_TOK * DIM];
__device__ __align__(256) bf16  g_kb  [(size_t)N_TOK * DIM];
__device__ __align__(256) bf16  g_gt  [(size_t)DIM * N_TOK];   // g^T [1024, 8192]
__device__ __align__(256) bf16  g_P   [(size_t)N_TOK * N_TOK]; // E = exp(c*s), bf16, 128 MB
__device__ float g_xpart[16 * DIM];
__device__ float g_xbar [DIM];
__device__ float g_muq  [DIM];
__device__ float g_muk  [DIM];
__device__ float g_csg  [DIM];
__device__ float g_m    [N_TOK];
__device__ float g_gate [N_TOK];
__device__ float g_inv  [N_TOK];    // 1 / row-sum of E

// ===================== small fp32 kernels =====================
__global__ void colmean_part(const float* __restrict__ x) {
    int col = blockIdx.x * 128 + threadIdx.x;
    int r0  = blockIdx.y * (N_TOK / 16);
    float s = 0.f;
    #pragma unroll 8
    for (int r = r0; r < r0 + N_TOK / 16; r++) s += x[(size_t)r * DIM + col];
    g_xpart[blockIdx.y * DIM + col] = s;
}
__global__ void colmean_finish() {
    int j = blockIdx.x * 256 + threadIdx.x;
    float s = 0.f;
    #pragma unroll
    for (int p = 0; p < 16; p++) s += g_xpart[p * DIM + j];
    g_xbar[j] = s * (1.0f / (float)N_TOK);
}
__global__ void mu_kernel(const float* __restrict__ Wq, const float* __restrict__ Wk,
                          const float* __restrict__ Wg) {
    __shared__ float sx[DIM];
    for (int i = threadIdx.x; i < DIM; i += 256) sx[i] = g_xbar[i];
    __syncthreads();
    int j = blockIdx.x * 256 + threadIdx.x;
    const float* W = (blockIdx.y == 0) ? Wq : (blockIdx.y == 1) ? Wk : Wg;
    float acc = 0.f;
    #pragma unroll 8
    for (int d = 0; d < DIM; d++) acc = fmaf(sx[d], W[(size_t)d * DIM + j], acc);
    if      (blockIdx.y == 0) g_muq[j] = acc;
    else if (blockIdx.y == 1) g_muk[j] = acc;
    else                      g_csg[j] = acc * (float)N_TOK;
}
__global__ void m_kernel(const float* __restrict__ x, const float* __restrict__ Wm_w,
                         const float* __restrict__ Wm_b) {
    int warp = threadIdx.x >> 5, lane = threadIdx.x & 31;
    int row  = blockIdx.x * 8 + warp;
    const float* xr = x + (size_t)row * DIM;
    float s = 0.f;
    #pragma unroll 8
    for (int t = lane; t < DIM; t += 32) s = fmaf(xr[t], Wm_w[t], s);
    #pragma unroll
    for (int o = 16; o > 0; o >>= 1) s += __shfl_xor_sync(0xffffffffu, s, o);
    if (lane == 0) g_m[row] = s + Wm_b[0];
}
__global__ void gate_kernel() {
    __shared__ float red[256];
    int tid = threadIdx.x;
    float mx = -1e30f;
    for (int i = tid; i < N_TOK; i += 256) mx = fmaxf(mx, g_m[i]);
    red[tid] = mx; __syncthreads();
    for (int o = 128; o > 0; o >>= 1) { if (tid < o) red[tid] = fmaxf(red[tid], red[tid + o]); __syncthreads(); }
    mx = red[0]; __syncthreads();
    float s = 0.f;
    for (int i = tid; i < N_TOK; i += 256) s += __expf(g_m[i] - mx);
    red[tid] = s; __syncthreads();
    for (int o = 128; o > 0; o >>= 1) { if (tid < o) red[tid] += red[tid + o]; __syncthreads(); }
    float inv = 1.f / red[0];
    for (int i = tid; i < N_TOK; i += 256) g_gate[i] = __expf(g_m[i] - mx) * inv;
}

// ===================== conversion kernels =====================
__global__ void tobf16_kernel(const float* __restrict__ in, bf16* __restrict__ outb, int n4) {
    int i = blockIdx.x * 256 + threadIdx.x;
    if (i >= n4) return;
    float4 v = reinterpret_cast<const float4*>(in)[i];
    reinterpret_cast<__nv_bfloat162*>(outb)[i*2+0] =
        __nv_bfloat162(__float2bfloat16(v.x), __float2bfloat16(v.y));
    reinterpret_cast<__nv_bfloat162*>(outb)[i*2+1] =
        __nv_bfloat162(__float2bfloat16(v.z), __float2bfloat16(v.w));
}
__global__ void trans_bf16_kernel(const float* __restrict__ W, bf16* __restrict__ T) {
    __shared__ float t[32][33];
    int bx = blockIdx.x * 32, by = blockIdx.y * 32;
    #pragma unroll
    for (int i = 0; i < 4; i++)
        t[threadIdx.y + 8*i][threadIdx.x] = W[(size_t)(by + threadIdx.y + 8*i) * DIM + bx + threadIdx.x];
    __syncthreads();
    #pragma unroll
    for (int i = 0; i < 4; i++)
        T[(size_t)(bx + threadIdx.y + 8*i) * DIM + by + threadIdx.x] =
            __float2bfloat16(t[threadIdx.x][threadIdx.y + 8*i]);
}

// ===================== row sums of E -> 1/sum =====================
__global__ void rowsum_inv(const bf16* __restrict__ E) {
    __shared__ float red[256];
    int row = blockIdx.x, tid = threadIdx.x;
    const __nv_bfloat162* Er = reinterpret_cast<const __nv_bfloat162*>(E + (size_t)row * N_TOK);
    float s = 0.f;
    #pragma unroll 4
    for (int j = tid; j < N_TOK / 2; j += 256) {
        __nv_bfloat162 v = Er[j];
        s += __bfloat162float(v.x) + __bfloat162float(v.y);
    }
    red[tid] = s; __syncthreads();
    for (int o = 128; o > 0; o >>= 1) { if (tid < o) red[tid] += red[tid + o]; __syncthreads(); }
    if (tid == 0) g_inv[row] = 1.f / red[0];
}

// ===================== mma.sync bf16 GEMM (ldmatrix mainloop) =====================
// C[M,Nc] = sum_k A[m,k]*B[n,k]  (B stored [Nc][K])
// MODE 0: outB = bf16(acc - subvec[col])  (subvec optional)
// MODE 2: outB = bf16(exp(acc * (*scaleptr)))
// MODE 3: outF = acc*invrow[row] + gate[row]*csum[col] + resid[row*DIM+col]
#define BK      32
#define STAGE_B (128 * 40 * 2 * 2)       // A half + B half = 20480 bytes
#define SMEM_GEMM (4 * STAGE_B)          // 81920

__device__ __forceinline__ uint32_t smem_u32(const void* p) {
    uint32_t addr;
    asm("{ .reg .u64 tmp; cvta.to.shared.u64 tmp, %1; cvt.u32.u64 %0, tmp; }"
        : "=r"(addr) : "l"(p));
    return addr;
}
#define CP_ASYNC16(dst_u32, src_ptr) \
    asm volatile("cp.async.cg.shared.global [%0], [%1], 16;" :: "r"(dst_u32), "l"(src_ptr) : "memory")
#define CP_COMMIT() asm volatile("cp.async.commit_group;" ::: "memory")
#define CP_WAIT2()  asm volatile("cp.async.wait_group 2;" ::: "memory")
#define LDSM_X4(r0, r1, r2, r3, addr) \
    asm volatile("ldmatrix.sync.aligned.m8n8.x4.shared.b16 {%0,%1,%2,%3}, [%4];" \
                 : "=r"(r0), "=r"(r1), "=r"(r2), "=r"(r3) : "r"(addr))

template<int MODE>
__global__ void __launch_bounds__(128, 2)
gemm1(int K,
      const bf16* __restrict__ A, const bf16* __restrict__ B,
      float* __restrict__ outF, bf16* __restrict__ outB,
      const float* __restrict__ subvec, const float* __restrict__ scaleptr,
      const float* __restrict__ gate, const float* __restrict__ csum,
      const float* __restrict__ resid, const float* __restrict__ invrow, int ldo)
{
    extern __shared__ char sm[];
    const int tid  = threadIdx.x;
    const int wid  = tid >> 5, lane = tid & 31;
    const int gid  = lane >> 2, tig = lane & 3;
    const int wm   = wid & 1, wn = wid >> 1;       // warp 64x64 tile: 2x2 layout
    const int row0 = blockIdx.y * 128;
    const int col0 = blockIdx.x * 128;
    const int NCH  = K / BK;
    const uint32_t smb = smem_u32(sm);

    // per-thread ldmatrix address offsets (within a 64-row half, 80B rows)
    const int aOff = (lane & 15) * 80 + (lane >> 4) * 16;
    const int bOff = (((lane < 16) ? 0 : 8) + (lane & 7)) * 80 + ((lane >> 3) & 1) * 16;

    float acc[4][8][4];
    #pragma unroll
    for (int i = 0; i < 4; i++)
        #pragma unroll
        for (int j = 0; j < 8; j++)
            #pragma unroll
            for (int t = 0; t < 4; t++) acc[i][j][t] = 0.f;

    auto loadChunk = [&](int c) {
        int kk = c * BK;
        uint32_t st = smb + (c & 3) * STAGE_B;
        #pragma unroll
        for (int it = 0; it < 4; ++it) {
            int idx = it * 128 + tid;
            int r = idx >> 2, ch = idx & 3;
            const bf16* ga = A + (size_t)(row0 + r) * K + kk + ch * 8;
            CP_ASYNC16(st + r * 80 + ch * 16, ga);
            const bf16* gb = B + (size_t)(col0 + r) * K + kk + ch * 8;
            CP_ASYNC16(st + 10240 + r * 80 + ch * 16, gb);
        }
    };

    loadChunk(0); CP_COMMIT();
    loadChunk(1); CP_COMMIT();
    loadChunk(2); CP_COMMIT();

    for (int c = 0; c < NCH; ++c) {
        CP_WAIT2();
        __syncthreads();
        {
            uint32_t sAb = smb + (c & 3) * STAGE_B + wm * 64 * 80 + aOff;
            uint32_t sBb = smb + (c & 3) * STAGE_B + 10240 + wn * 64 * 80 + bOff;
            uint32_t a[2][4][4], b[2][8][2];
            #pragma unroll
            for (int h = 0; h < 2; ++h) {
                int kb = h * 32;                      // byte offset of k16 half
                #pragma unroll
                for (int mt = 0; mt < 4; ++mt)
                    LDSM_X4(a[h][mt][0], a[h][mt][1], a[h][mt][2], a[h][mt][3],
                            sAb + mt * 1280 + kb);
                #pragma unroll
                for (int p = 0; p < 4; ++p)
                    LDSM_X4(b[h][2*p][0], b[h][2*p][1], b[h][2*p+1][0], b[h][2*p+1][1],
                            sBb + p * 1280 + kb);
            }
            #pragma unroll
            for (int h = 0; h < 2; ++h)
                #pragma unroll
                for (int mt = 0; mt < 4; ++mt)
                    #pragma unroll
                    for (int nt = 0; nt < 8; ++nt)
                        asm volatile(
                            "mma.sync.aligned.m16n8k16.row.col.f32.bf16.bf16.f32 "
                            "{%0,%1,%2,%3}, {%4,%5,%6,%7}, {%8,%9}, {%0,%1,%2,%3};"
                            : "+f"(acc[mt][nt][0]), "+f"(acc[mt][nt][1]),
                              "+f"(acc[mt][nt][2]), "+f"(acc[mt][nt][3])
                            : "r"(a[h][mt][0]), "r"(a[h][mt][1]), "r"(a[h][mt][2]), "r"(a[h][mt][3]),
                              "r"(b[h][nt][0]), "r"(b[h][nt][1]));
        }
        if (c + 3 < NCH) loadChunk(c + 3);
        CP_COMMIT();
    }

    // ---------------- epilogue ----------------
    float scale = (MODE == 2) ? *scaleptr : 1.0f;
    #pragma unroll
    for (int mt = 0; mt < 4; ++mt) {
        int r1 = row0 + wm * 64 + mt * 16 + gid;
        int r2 = r1 + 8;
        float gv1 = 0.f, gv2 = 0.f, iv1 = 1.f, iv2 = 1.f;
        if (MODE == 3) {
            gv1 = gate[r1]; gv2 = gate[r2];
            iv1 = invrow[r1]; iv2 = invrow[r2];
        }
        #pragma unroll
        for (int nt = 0; nt < 8; ++nt) {
            int col = col0 + wn * 64 + nt * 8 + tig * 2;
            float c0 = acc[mt][nt][0], c1 = acc[mt][nt][1];
            float c2 = acc[mt][nt][2], c3 = acc[mt][nt][3];
            if (MODE == 0) {
                if (subvec) {
                    float s0 = subvec[col], s1 = subvec[col + 1];
                    c0 -= s0; c1 -= s1; c2 -= s0; c3 -= s1;
                }
                *reinterpret_cast<__nv_bfloat162*>(outB + (size_t)r1 * ldo + col) =
                    __nv_bfloat162(__float2bfloat16(c0), __float2bfloat16(c1));
                *reinterpret_cast<__nv_bfloat162*>(outB + (size_t)r2 * ldo + col) =
                    __nv_bfloat162(__float2bfloat16(c2), __float2bfloat16(c3));
            } else if (MODE == 2) {
                float e0 = __expf(c0 * scale), e1 = __expf(c1 * scale);
                float e2 = __expf(c2 * scale), e3 = __expf(c3 * scale);
                *reinterpret_cast<__nv_bfloat162*>(outB + (size_t)r1 * ldo + col) =
                    __nv_bfloat162(__float2bfloat16(e0), __float2bfloat16(e1));
                *reinterpret_cast<__nv_bfloat162*>(outB + (size_t)r2 * ldo + col) =
                    __nv_bfloat162(__float2bfloat16(e2), __float2bfloat16(e3));
            } else {
                float cs0 = csum[col], cs1 = csum[col + 1];
                float2 x1 = *reinterpret_cast<const float2*>(resid + (size_t)r1 * DIM + col);
                float2 x2 = *reinterpret_cast<const float2*>(resid + (size_t)r2 * DIM + col);
                *reinterpret_cast<float2*>(outF + (size_t)r1 * ldo + col) =
                    make_float2(c0 * iv1 + gv1 * cs0 + x1.x, c1 * iv1 + gv1 * cs1 + x1.y);
                *reinterpret_cast<float2*>(outF + (size_t)r2 * ldo + col) =
                    make_float2(c2 * iv2 + gv2 * cs0 + x2.x, c3 * iv2 + gv2 * cs1 + x2.y);
            }
        }
    }
}

// ===================== launch =====================
extern "C" void kernel_launch(void* const* d_in, const int* in_sizes, int n_in,
                              void* d_out, int out_size) {
    const float* x    = (const float*)d_in[0];
    const float* Wq   = (const float*)d_in[1];
    const float* Wk   = (const float*)d_in[2];
    const float* Wg   = (const float*)d_in[3];
    const float* Wm_w = (const float*)d_in[4];
    const float* Wm_b = (const float*)d_in[5];
    const float* cp   = (const float*)d_in[6];
    float* out = (float*)d_out;

    bf16 *xb,*wqt,*wkt,*wgt,*qb,*kb,*gt,*P;
    float *muq,*muk,*csg,*gate,*inv;
    cudaGetSymbolAddress((void**)&xb,  g_xb);
    cudaGetSymbolAddress((void**)&wqt, g_wqt);
    cudaGetSymbolAddress((void**)&wkt, g_wkt);
    cudaGetSymbolAddress((void**)&wgt, g_wgt);
    cudaGetSymbolAddress((void**)&qb,  g_qb);
    cudaGetSymbolAddress((void**)&kb,  g_kb);
    cudaGetSymbolAddress((void**)&gt,  g_gt);
    cudaGetSymbolAddress((void**)&P,   g_P);
    cudaGetSymbolAddress((void**)&muq, g_muq);
    cudaGetSymbolAddress((void**)&muk, g_muk);
    cudaGetSymbolAddress((void**)&csg, g_csg);
    cudaGetSymbolAddress((void**)&gate, g_gate);
    cudaGetSymbolAddress((void**)&inv, g_inv);

    cudaFuncSetAttribute(gemm1<0>, cudaFuncAttributeMaxDynamicSharedMemorySize, SMEM_GEMM);
    cudaFuncSetAttribute(gemm1<2>, cudaFuncAttributeMaxDynamicSharedMemorySize, SMEM_GEMM);
    cudaFuncSetAttribute(gemm1<3>, cudaFuncAttributeMaxDynamicSharedMemorySize, SMEM_GEMM);

    // stats + conversions
    colmean_part<<<dim3(8, 16), 128>>>(x);
    colmean_finish<<<4, 256>>>();
    mu_kernel<<<dim3(4, 3), 256>>>(Wq, Wk, Wg);
    m_kernel<<<1024, 256>>>(x, Wm_w, Wm_b);
    gate_kernel<<<1, 256>>>();
    tobf16_kernel<<<(N_TOK * DIM / 4 + 255) / 256, 256>>>(x, xb, N_TOK * DIM / 4);
    trans_bf16_kernel<<<dim3(32, 32), dim3(32, 8)>>>(Wq, wqt);
    trans_bf16_kernel<<<dim3(32, 32), dim3(32, 8)>>>(Wk, wkt);
    trans_bf16_kernel<<<dim3(32, 32), dim3(32, 8)>>>(Wg, wgt);

    // q = x@Wq - muq ; k = x@Wk - muk
    gemm1<0><<<dim3(DIM / 128, N_TOK / 128), 128, SMEM_GEMM>>>(
        DIM, xb, wqt, nullptr, qb, muq, nullptr, nullptr, nullptr, nullptr, nullptr, DIM);
    gemm1<0><<<dim3(DIM / 128, N_TOK / 128), 128, SMEM_GEMM>>>(
        DIM, xb, wkt, nullptr, kb, muk, nullptr, nullptr, nullptr, nullptr, nullptr, DIM);
    // gT = Wg^T @ x^T : out [1024, 8192]
    gemm1<0><<<dim3(N_TOK / 128, DIM / 128), 128, SMEM_GEMM>>>(
        DIM, wgt, xb, nullptr, gt, nullptr, nullptr, nullptr, nullptr, nullptr, nullptr, N_TOK);

    // E = bf16(exp(c * q @ k^T))   (softmax numerator; scores are O(1)-bounded)
    gemm1<2><<<dim3(N_TOK / 128, N_TOK / 128), 128, SMEM_GEMM>>>(
        DIM, qb, kb, nullptr, P, nullptr, cp, nullptr, nullptr, nullptr, nullptr, N_TOK);

    // inv[row] = 1 / sum_j E[row][j]
    rowsum_inv<<<N_TOK, 256>>>(P);

    // out = (E @ g) * inv[row] + gate[row]*csg[col] + x
    gemm1<3><<<dim3(DIM / 128, N_TOK / 128), 128, SMEM_GEMM>>>(
        N_TOK, P, gt, out, nullptr, nullptr, nullptr, gate, csg, x, inv, DIM);
}